// round 8
// baseline (speedup 1.0000x reference)
#include <cuda_runtime.h>

#define HH 4
#define BB 32
#define NNODE 14
#define FF 1024
#define NF (NNODE*FF)   // 14336
#define KSPLIT 152      // k3 partial slices (h*38 + kc)

#define ALPHA_SLOPE 0.2f
#define NEGV (-9000000000000000.0f)

// Scratch (no allocation allowed)
static __device__ float g_hp[HH*BB*NNODE*FF];     // 7 MB
static __device__ float g_part[KSPLIT*BB*FF];     // 19 MB

// ---- packed fp32x2 helpers ----
__device__ __forceinline__ unsigned long long pk2(float a, float b){
    unsigned long long r;
    asm("mov.b64 %0, {%1, %2};" : "=l"(r) : "f"(a), "f"(b));
    return r;
}
__device__ __forceinline__ void fma2(unsigned long long &d, unsigned long long a, unsigned long long b){
    asm("fma.rn.f32x2 %0, %1, %2, %0;" : "+l"(d) : "l"(a), "l"(b));
}
__device__ __forceinline__ float2 upk(unsigned long long v){
    float2 r;
    asm("mov.b64 {%0, %1}, %2;" : "=f"(r.x), "=f"(r.y) : "l"(v));
    return r;
}

// ---- cp.async helpers ----
__device__ __forceinline__ unsigned su32(const void* p){
    return (unsigned)__cvta_generic_to_shared(p);
}
__device__ __forceinline__ void cpasync16(unsigned dst, const void* src){
    asm volatile("cp.async.cg.shared.global [%0], [%1], 16;\n" :: "r"(dst), "l"(src));
}
__device__ __forceinline__ void cpcommit(){ asm volatile("cp.async.commit_group;\n" ::: "memory"); }
template<int N> __device__ __forceinline__ void cpwait(){
    asm volatile("cp.async.wait_group %0;\n" :: "n"(N) : "memory");
}

// ---- tf32 mma.sync (m16n8k8), D += A*B, fp32 accum ----
__device__ __forceinline__ void mma_tf32(float* d,
    unsigned a0, unsigned a1, unsigned a2, unsigned a3,
    unsigned b0, unsigned b1){
    asm volatile("mma.sync.aligned.m16n8k8.row.col.f32.tf32.tf32.f32 "
        "{%0,%1,%2,%3}, {%4,%5,%6,%7}, {%8,%9}, {%0,%1,%2,%3};\n"
        : "+f"(d[0]), "+f"(d[1]), "+f"(d[2]), "+f"(d[3])
        : "r"(a0), "r"(a1), "r"(a2), "r"(a3), "r"(b0), "r"(b1));
}

#define TF32_MASK 0xFFFFE000u   // keep sign+exp+top10 mantissa

// ============================================================================
// K1 (fused with attention) — profiled at 6.27 TB/s (HBM roofline): UNCHANGED.
// ============================================================================
#define K1_PITCH 1032
#define K1_SMEM ((16*K1_PITCH + 2*16*K1_PITCH)*4)

__global__ __launch_bounds__(256) void k1_wh(const float* __restrict__ x,
                                             const float* __restrict__ W,
                                             const float* __restrict__ adj,
                                             const float* __restrict__ attv){
    extern __shared__ float smem[];
    float* sA = smem;                       // [16][1032]
    float* sB = smem + 16*K1_PITCH;         // [2][16][1032]

    __shared__ float s_s1[NNODE], s_s2[NNODE];
    __shared__ float satt[NNODE][NNODE];
    __shared__ float red[2*NNODE][8];

    const int hb   = blockIdx.x;
    const int b    = hb & (BB-1);
    const int tid  = threadIdx.x;
    const int lane = tid & 31;
    const int w    = tid >> 5;

    const float* xb = x + (size_t)b * NNODE * FF;
    const float* Wp = W + (size_t)hb * FF * FF;

    float acc[16][4];
#pragma unroll
    for(int j=0;j<16;j++){ acc[j][0]=0.f; acc[j][1]=0.f; acc[j][2]=0.f; acc[j][3]=0.f; }

    {
#pragma unroll
        for(int j=0;j<16;j++){
            int idx = tid + j*256;
            int r   = idx >> 8;
            int n4  = (idx & 255) << 2;
            cpasync16(su32(&sB[r*K1_PITCH + n4]), Wp + r*FF + n4);
        }
        cpcommit();
    }

#pragma unroll
    for(int j=0;j<16;j++){
        int idx = tid + j*256;
        int r   = idx >> 8;
        int k4  = (idx & 255) << 2;
        float4 v = make_float4(0.f,0.f,0.f,0.f);
        if(r < NNODE) v = *(const float4*)(xb + r*FF + k4);
        *(float4*)(&sA[r*K1_PITCH + k4]) = v;
    }

    const int ar = lane >> 2;
    const int ak = lane & 3;

    for(int c=0;c<64;c++){
        const int buf = c & 1;
        if(c < 63){
            const float* src = Wp + (size_t)(c+1)*16*FF;
#pragma unroll
            for(int j=0;j<16;j++){
                int idx = tid + j*256;
                int r   = idx >> 8;
                int n4  = (idx & 255) << 2;
                cpasync16(su32(&sB[((buf^1)*16 + r)*K1_PITCH + n4]), src + r*FF + n4);
            }
            cpcommit();
            cpwait<1>();
        } else {
            cpwait<0>();
        }
        __syncthreads();

        const float* Bb = &sB[buf*16*K1_PITCH];
#pragma unroll
        for(int kh=0;kh<2;kh++){
            const int k0 = kh*8;
            const int ac = c*16 + k0 + ak;
            float a0f = sA[ar*K1_PITCH + ac];
            float a1f = sA[(ar+8)*K1_PITCH + ac];
            float a2f = sA[ar*K1_PITCH + ac + 4];
            float a3f = sA[(ar+8)*K1_PITCH + ac + 4];
            unsigned h0 = __float_as_uint(a0f) & TF32_MASK;
            unsigned h1 = __float_as_uint(a1f) & TF32_MASK;
            unsigned h2 = __float_as_uint(a2f) & TF32_MASK;
            unsigned h3 = __float_as_uint(a3f) & TF32_MASK;
            unsigned l0 = __float_as_uint(a0f - __uint_as_float(h0));
            unsigned l1 = __float_as_uint(a1f - __uint_as_float(h1));
            unsigned l2 = __float_as_uint(a2f - __uint_as_float(h2));
            unsigned l3 = __float_as_uint(a3f - __uint_as_float(h3));
#pragma unroll
            for(int j=0;j<16;j++){
                int nb = w*128 + j*8 + (lane>>2);
                unsigned b0 = __float_as_uint(Bb[(k0 + ak)*K1_PITCH + nb]);
                unsigned b1 = __float_as_uint(Bb[(k0 + ak + 4)*K1_PITCH + nb]);
                mma_tf32(acc[j], h0,h1,h2,h3, b0,b1);
                mma_tf32(acc[j], l0,l1,l2,l3, b0,b1);
            }
        }
        __syncthreads();
    }

    // ---- fused attention epilogue ----
    float* sWh = sB;   // [16][1032]
    {
        const int r0 = lane >> 2;
#pragma unroll
        for(int j=0;j<16;j++){
            int col = w*128 + j*8 + 2*(lane&3);
            sWh[r0*K1_PITCH + col]     = acc[j][0];
            sWh[r0*K1_PITCH + col + 1] = acc[j][1];
            sWh[(r0+8)*K1_PITCH + col]     = acc[j][2];
            sWh[(r0+8)*K1_PITCH + col + 1] = acc[j][3];
        }
    }
    __syncthreads();

    const int c0 = tid * 4;
    const float* av = attv + (size_t)hb * 2 * FF;
    {
        float4 a1v = *(const float4*)(av + c0);
        float4 a2v = *(const float4*)(av + FF + c0);
        float p1[NNODE], p2[NNODE];
#pragma unroll
        for(int n=0;n<NNODE;n++){
            float4 wv = *(const float4*)(&sWh[n*K1_PITCH + c0]);
            p1[n] = wv.x*a1v.x + wv.y*a1v.y + wv.z*a1v.z + wv.w*a1v.w;
            p2[n] = wv.x*a2v.x + wv.y*a2v.y + wv.z*a2v.z + wv.w*a2v.w;
        }
#pragma unroll
        for(int n=0;n<NNODE;n++){
#pragma unroll
            for(int off=16;off;off>>=1){
                p1[n] += __shfl_xor_sync(0xFFFFFFFFu, p1[n], off);
                p2[n] += __shfl_xor_sync(0xFFFFFFFFu, p2[n], off);
            }
        }
        if(lane==0){
#pragma unroll
            for(int n=0;n<NNODE;n++){ red[n][w]=p1[n]; red[NNODE+n][w]=p2[n]; }
        }
    }
    __syncthreads();
    if(tid < 2*NNODE){
        float s=0.f;
#pragma unroll
        for(int q=0;q<8;q++) s += red[tid][q];
        if(tid < NNODE) s_s1[tid] = s; else s_s2[tid-NNODE] = s;
    }
    __syncthreads();

    if(tid < NNODE){
        int m = tid;
        float col[NNODE];
        float mx = -3.4e38f;
#pragma unroll
        for(int n=0;n<NNODE;n++){
            float e = s_s1[n] + s_s2[m];
            e = (e > 0.f) ? e : ALPHA_SLOPE*e;
            float v = (adj[(size_t)b*NNODE*NNODE + n*NNODE + m] > 0.f) ? e : NEGV;
            col[n] = v;
            mx = fmaxf(mx, v);
        }
        float sum = 0.f;
#pragma unroll
        for(int n=0;n<NNODE;n++){
            col[n] = expf(col[n]-mx);
            sum += col[n];
        }
        float inv = 1.f/sum;
#pragma unroll
        for(int n=0;n<NNODE;n++) satt[n][m] = col[n]*inv;
    }
    __syncthreads();

    {
        unsigned long long hp01[NNODE], hp23[NNODE];
#pragma unroll
        for(int n=0;n<NNODE;n++){ hp01[n]=0ull; hp23[n]=0ull; }
#pragma unroll
        for(int m=0;m<NNODE;m++){
            float4 wv = *(const float4*)(&sWh[m*K1_PITCH + c0]);
            unsigned long long w01 = pk2(wv.x,wv.y);
            unsigned long long w23 = pk2(wv.z,wv.w);
#pragma unroll
            for(int n=0;n<NNODE;n++){
                float at = satt[n][m];
                unsigned long long ap = pk2(at,at);
                fma2(hp01[n], ap, w01);
                fma2(hp23[n], ap, w23);
            }
        }
        float* outp = g_hp + (size_t)hb * NF + c0;
#pragma unroll
        for(int n=0;n<NNODE;n++){
            float2 q0 = upk(hp01[n]);
            float2 q1 = upk(hp23[n]);
            *(float4*)(outp + (size_t)n*FF) = make_float4(q0.x,q0.y,q1.x,q1.y);
        }
    }
}

// ============================================================================
// K3: split-K tf32 GEMM over fc: part[h*38+kc][b][o-half]
// Grid 304 = 4h x 2ot(512 o's) x 38kc  -> exactly 2 sequential CTAs per SM.
// 512 threads (16 warps, 32 o's each). Depth-3 cp.async, chunk = 16k x 512o.
// Variable chunk widths: kc<22 -> 24 sixteens (384), else 23 (368). Sum=14336.
// ============================================================================
#define K3_PITCH 20
#define K3_SMEM (3*(512*K3_PITCH + 32*K3_PITCH)*4)   // 130,560 B

__global__ __launch_bounds__(512) void k3_fc(const float* __restrict__ fcw){
    extern __shared__ float s3[];
    float* sB = s3;                          // [3][512][20]
    float* sA = s3 + 3*512*K3_PITCH;         // [3][32][20]

    const int blk = blockIdx.x;              // h*76 + ot*38 + kc
    const int h   = blk / 76;
    const int rem = blk % 76;
    const int ot  = rem / 38;
    const int kc  = rem % 38;

    const int niter = (kc < 22) ? 24 : 23;                       // 16-float steps
    const int f0    = 16 * ((kc < 22) ? kc*24 : 22*24 + (kc-22)*23);

    const int tid  = threadIdx.x;
    const int lane = tid & 31;
    const int w    = tid >> 5;               // 0..15

    const float* hpB = g_hp + (size_t)h * BB * NF;
    const float* wB  = fcw  + (size_t)h * FF * NF + (size_t)(ot*512) * NF;

    float acc[2][4][4];
#pragma unroll
    for(int mt=0;mt<2;mt++)
#pragma unroll
    for(int j=0;j<4;j++){ acc[mt][j][0]=0.f; acc[mt][j][1]=0.f; acc[mt][j][2]=0.f; acc[mt][j][3]=0.f; }

    auto issue = [&](int cc){
        const int s  = cc % 3;
        const int fb = f0 + cc*16;
#pragma unroll
        for(int j=0;j<4;j++){
            int idx = tid + j*512;           // 2048 float4 (512 o x 4)
            int o   = idx >> 2;
            int f4  = (idx & 3) << 2;
            cpasync16(su32(&sB[(s*512 + o)*K3_PITCH + f4]), wB + (size_t)o*NF + fb + f4);
        }
        if(tid < 128){
            int bq = tid >> 2;
            int f4 = (tid & 3) << 2;
            cpasync16(su32(&sA[(s*32 + bq)*K3_PITCH + f4]), hpB + (size_t)bq*NF + fb + f4);
        }
        cpcommit();
    };

    issue(0); issue(1);

    const int ak = lane & 3;
    const int ar = lane >> 2;

    for(int c=0;c<niter;c++){
        if(c+1 < niter) cpwait<1>();
        else            cpwait<0>();
        __syncthreads();
        if(c+2 < niter) issue(c+2);          // stage (c+2)%3 == (c-1)%3, drained

        const int s = c % 3;
        const float* sAs = &sA[s*32*K3_PITCH];
        const float* sBs = &sB[s*512*K3_PITCH];
#pragma unroll
        for(int kh=0;kh<2;kh++){
            const int k0 = kh*8;
            unsigned hfr[2][4], lfr[2][4];
#pragma unroll
            for(int mt=0;mt<2;mt++){
                float a0f = sAs[(mt*16 + ar    )*K3_PITCH + k0 + ak];
                float a1f = sAs[(mt*16 + ar + 8)*K3_PITCH + k0 + ak];
                float a2f = sAs[(mt*16 + ar    )*K3_PITCH + k0 + ak + 4];
                float a3f = sAs[(mt*16 + ar + 8)*K3_PITCH + k0 + ak + 4];
                hfr[mt][0] = __float_as_uint(a0f) & TF32_MASK;
                hfr[mt][1] = __float_as_uint(a1f) & TF32_MASK;
                hfr[mt][2] = __float_as_uint(a2f) & TF32_MASK;
                hfr[mt][3] = __float_as_uint(a3f) & TF32_MASK;
                lfr[mt][0] = __float_as_uint(a0f - __uint_as_float(hfr[mt][0]));
                lfr[mt][1] = __float_as_uint(a1f - __uint_as_float(hfr[mt][1]));
                lfr[mt][2] = __float_as_uint(a2f - __uint_as_float(hfr[mt][2]));
                lfr[mt][3] = __float_as_uint(a3f - __uint_as_float(hfr[mt][3]));
            }
#pragma unroll
            for(int j=0;j<4;j++){
                int nb = w*32 + j*8 + (lane>>2);
                unsigned b0 = __float_as_uint(sBs[nb*K3_PITCH + k0 + ak]);
                unsigned b1 = __float_as_uint(sBs[nb*K3_PITCH + k0 + ak + 4]);
                mma_tf32(acc[0][j], hfr[0][0],hfr[0][1],hfr[0][2],hfr[0][3], b0,b1);
                mma_tf32(acc[0][j], lfr[0][0],lfr[0][1],lfr[0][2],lfr[0][3], b0,b1);
                mma_tf32(acc[1][j], hfr[1][0],hfr[1][1],hfr[1][2],hfr[1][3], b0,b1);
                mma_tf32(acc[1][j], lfr[1][0],lfr[1][1],lfr[1][2],lfr[1][3], b0,b1);
            }
        }
    }

    const int kbi = h*38 + kc;
    float* pp = g_part + (size_t)kbi * BB * FF;
#pragma unroll
    for(int mt=0;mt<2;mt++)
#pragma unroll
    for(int j=0;j<4;j++){
        int col = ot*512 + w*32 + j*8 + 2*(lane&3);
        int r   = mt*16 + (lane>>2);
        *(float2*)(pp + (size_t)r*FF + col)     = make_float2(acc[mt][j][0], acc[mt][j][1]);
        *(float2*)(pp + (size_t)(r+8)*FF + col) = make_float2(acc[mt][j][2], acc[mt][j][3]);
    }
}

// ============================================================================
// K4 (fused): out[b,:] = log_softmax( sum_kb part[kb][b][:] + sum_h fcb[h][:] )
// 32 blocks x 1024 threads (1 o per thread), 152 slices, unroll 8.
// ============================================================================
__global__ __launch_bounds__(1024) void k4_out(const float* __restrict__ fcb,
                                               float* __restrict__ out){
    const int b   = blockIdx.x;
    const int o   = threadIdx.x;
    const int wid = o >> 5, lid = o & 31;

    __shared__ float sred[32];

    float s = 0.f;
#pragma unroll 8
    for(int kb=0;kb<KSPLIT;kb++)
        s += g_part[((size_t)kb*BB + b)*FF + o];
    float bias = 0.f;
#pragma unroll
    for(int h=0;h<HH;h++) bias += fcb[h*FF + o];
    float v = s + bias;

    float mx = v;
#pragma unroll
    for(int off=16;off;off>>=1) mx = fmaxf(mx, __shfl_xor_sync(0xFFFFFFFFu, mx, off));
    if(lid==0) sred[wid]=mx;
    __syncthreads();
    if(wid==0){
        float m = sred[lid];
#pragma unroll
        for(int off=16;off;off>>=1) m = fmaxf(m, __shfl_xor_sync(0xFFFFFFFFu, m, off));
        if(lid==0) sred[0]=m;
    }
    __syncthreads();
    float bm = sred[0];
    __syncthreads();

    float e = expf(v-bm);
    float sm = e;
#pragma unroll
    for(int off=16;off;off>>=1) sm += __shfl_xor_sync(0xFFFFFFFFu, sm, off);
    if(lid==0) sred[wid]=sm;
    __syncthreads();
    if(wid==0){
        float t = sred[lid];
#pragma unroll
        for(int off=16;off;off>>=1) t += __shfl_xor_sync(0xFFFFFFFFu, t, off);
        if(lid==0) sred[0]=t;
    }
    __syncthreads();
    float lse = bm + logf(sred[0]);

    out[(size_t)b*FF + o] = v - lse;
}

// ============================================================================
extern "C" void kernel_launch(void* const* d_in, const int* in_sizes, int n_in,
                              void* d_out, int out_size){
    const float* x   = (const float*)d_in[0];
    const float* adj = (const float*)d_in[1];
    const float* W   = (const float*)d_in[2];
    const float* a   = (const float*)d_in[3];
    const float* fcw = (const float*)d_in[4];
    const float* fcb = (const float*)d_in[5];
    float* out = (float*)d_out;

    cudaFuncSetAttribute(k1_wh, cudaFuncAttributeMaxDynamicSharedMemorySize, K1_SMEM);
    cudaFuncSetAttribute(k3_fc, cudaFuncAttributeMaxDynamicSharedMemorySize, K3_SMEM);

    k1_wh <<<HH*BB, 256, K1_SMEM>>>(x, W, adj, a);
    k3_fc <<<304, 512, K3_SMEM>>>(fcw);
    k4_out<<<BB, 1024>>>(fcb, out);
}

// round 9
// speedup vs baseline: 1.1487x; 1.1487x over previous
#include <cuda_runtime.h>

#define HH 4
#define BB 32
#define NNODE 14
#define FF 1024
#define NF (NNODE*FF)   // 14336
#define KSPLIT 76       // k3 partial slices (h*19 + kc)

#define ALPHA_SLOPE 0.2f
#define NEGV (-9000000000000000.0f)

// Scratch (no allocation allowed)
static __device__ float g_hp[HH*BB*NNODE*FF];     // 7 MB
static __device__ float g_part[KSPLIT*BB*FF];     // 9.5 MB

// ---- packed fp32x2 helpers ----
__device__ __forceinline__ unsigned long long pk2(float a, float b){
    unsigned long long r;
    asm("mov.b64 %0, {%1, %2};" : "=l"(r) : "f"(a), "f"(b));
    return r;
}
__device__ __forceinline__ void fma2(unsigned long long &d, unsigned long long a, unsigned long long b){
    asm("fma.rn.f32x2 %0, %1, %2, %0;" : "+l"(d) : "l"(a), "l"(b));
}
__device__ __forceinline__ float2 upk(unsigned long long v){
    float2 r;
    asm("mov.b64 {%0, %1}, %2;" : "=f"(r.x), "=f"(r.y) : "l"(v));
    return r;
}

// ---- cp.async helpers ----
__device__ __forceinline__ unsigned su32(const void* p){
    return (unsigned)__cvta_generic_to_shared(p);
}
__device__ __forceinline__ void cpasync16(unsigned dst, const void* src){
    asm volatile("cp.async.cg.shared.global [%0], [%1], 16;\n" :: "r"(dst), "l"(src));
}
__device__ __forceinline__ void cpcommit(){ asm volatile("cp.async.commit_group;\n" ::: "memory"); }
template<int N> __device__ __forceinline__ void cpwait(){
    asm volatile("cp.async.wait_group %0;\n" :: "n"(N) : "memory");
}

// ---- tf32 mma.sync (m16n8k8), D += A*B, fp32 accum ----
__device__ __forceinline__ void mma_tf32(float* d,
    unsigned a0, unsigned a1, unsigned a2, unsigned a3,
    unsigned b0, unsigned b1){
    asm volatile("mma.sync.aligned.m16n8k8.row.col.f32.tf32.tf32.f32 "
        "{%0,%1,%2,%3}, {%4,%5,%6,%7}, {%8,%9}, {%0,%1,%2,%3};\n"
        : "+f"(d[0]), "+f"(d[1]), "+f"(d[2]), "+f"(d[3])
        : "r"(a0), "r"(a1), "r"(a2), "r"(a3), "r"(b0), "r"(b1));
}

#define TF32_MASK 0xFFFFE000u   // keep sign+exp+top10 mantissa

// ============================================================================
// K1 (fused with attention) — profiled at 6.27 TB/s (HBM roofline): UNCHANGED.
// ============================================================================
#define K1_PITCH 1032
#define K1_SMEM ((16*K1_PITCH + 2*16*K1_PITCH)*4)

__global__ __launch_bounds__(256) void k1_wh(const float* __restrict__ x,
                                             const float* __restrict__ W,
                                             const float* __restrict__ adj,
                                             const float* __restrict__ attv){
    extern __shared__ float smem[];
    float* sA = smem;                       // [16][1032]
    float* sB = smem + 16*K1_PITCH;         // [2][16][1032]

    __shared__ float s_s1[NNODE], s_s2[NNODE];
    __shared__ float satt[NNODE][NNODE];
    __shared__ float red[2*NNODE][8];

    const int hb   = blockIdx.x;
    const int b    = hb & (BB-1);
    const int tid  = threadIdx.x;
    const int lane = tid & 31;
    const int w    = tid >> 5;

    const float* xb = x + (size_t)b * NNODE * FF;
    const float* Wp = W + (size_t)hb * FF * FF;

    float acc[16][4];
#pragma unroll
    for(int j=0;j<16;j++){ acc[j][0]=0.f; acc[j][1]=0.f; acc[j][2]=0.f; acc[j][3]=0.f; }

    {
#pragma unroll
        for(int j=0;j<16;j++){
            int idx = tid + j*256;
            int r   = idx >> 8;
            int n4  = (idx & 255) << 2;
            cpasync16(su32(&sB[r*K1_PITCH + n4]), Wp + r*FF + n4);
        }
        cpcommit();
    }

#pragma unroll
    for(int j=0;j<16;j++){
        int idx = tid + j*256;
        int r   = idx >> 8;
        int k4  = (idx & 255) << 2;
        float4 v = make_float4(0.f,0.f,0.f,0.f);
        if(r < NNODE) v = *(const float4*)(xb + r*FF + k4);
        *(float4*)(&sA[r*K1_PITCH + k4]) = v;
    }

    const int ar = lane >> 2;
    const int ak = lane & 3;

    for(int c=0;c<64;c++){
        const int buf = c & 1;
        if(c < 63){
            const float* src = Wp + (size_t)(c+1)*16*FF;
#pragma unroll
            for(int j=0;j<16;j++){
                int idx = tid + j*256;
                int r   = idx >> 8;
                int n4  = (idx & 255) << 2;
                cpasync16(su32(&sB[((buf^1)*16 + r)*K1_PITCH + n4]), src + r*FF + n4);
            }
            cpcommit();
            cpwait<1>();
        } else {
            cpwait<0>();
        }
        __syncthreads();

        const float* Bb = &sB[buf*16*K1_PITCH];
#pragma unroll
        for(int kh=0;kh<2;kh++){
            const int k0 = kh*8;
            const int ac = c*16 + k0 + ak;
            float a0f = sA[ar*K1_PITCH + ac];
            float a1f = sA[(ar+8)*K1_PITCH + ac];
            float a2f = sA[ar*K1_PITCH + ac + 4];
            float a3f = sA[(ar+8)*K1_PITCH + ac + 4];
            unsigned h0 = __float_as_uint(a0f) & TF32_MASK;
            unsigned h1 = __float_as_uint(a1f) & TF32_MASK;
            unsigned h2 = __float_as_uint(a2f) & TF32_MASK;
            unsigned h3 = __float_as_uint(a3f) & TF32_MASK;
            unsigned l0 = __float_as_uint(a0f - __uint_as_float(h0));
            unsigned l1 = __float_as_uint(a1f - __uint_as_float(h1));
            unsigned l2 = __float_as_uint(a2f - __uint_as_float(h2));
            unsigned l3 = __float_as_uint(a3f - __uint_as_float(h3));
#pragma unroll
            for(int j=0;j<16;j++){
                int nb = w*128 + j*8 + (lane>>2);
                unsigned b0 = __float_as_uint(Bb[(k0 + ak)*K1_PITCH + nb]);
                unsigned b1 = __float_as_uint(Bb[(k0 + ak + 4)*K1_PITCH + nb]);
                mma_tf32(acc[j], h0,h1,h2,h3, b0,b1);
                mma_tf32(acc[j], l0,l1,l2,l3, b0,b1);
            }
        }
        __syncthreads();
    }

    // ---- fused attention epilogue ----
    float* sWh = sB;   // [16][1032]
    {
        const int r0 = lane >> 2;
#pragma unroll
        for(int j=0;j<16;j++){
            int col = w*128 + j*8 + 2*(lane&3);
            sWh[r0*K1_PITCH + col]     = acc[j][0];
            sWh[r0*K1_PITCH + col + 1] = acc[j][1];
            sWh[(r0+8)*K1_PITCH + col]     = acc[j][2];
            sWh[(r0+8)*K1_PITCH + col + 1] = acc[j][3];
        }
    }
    __syncthreads();

    const int c0 = tid * 4;
    const float* av = attv + (size_t)hb * 2 * FF;
    {
        float4 a1v = *(const float4*)(av + c0);
        float4 a2v = *(const float4*)(av + FF + c0);
        float p1[NNODE], p2[NNODE];
#pragma unroll
        for(int n=0;n<NNODE;n++){
            float4 wv = *(const float4*)(&sWh[n*K1_PITCH + c0]);
            p1[n] = wv.x*a1v.x + wv.y*a1v.y + wv.z*a1v.z + wv.w*a1v.w;
            p2[n] = wv.x*a2v.x + wv.y*a2v.y + wv.z*a2v.z + wv.w*a2v.w;
        }
#pragma unroll
        for(int n=0;n<NNODE;n++){
#pragma unroll
            for(int off=16;off;off>>=1){
                p1[n] += __shfl_xor_sync(0xFFFFFFFFu, p1[n], off);
                p2[n] += __shfl_xor_sync(0xFFFFFFFFu, p2[n], off);
            }
        }
        if(lane==0){
#pragma unroll
            for(int n=0;n<NNODE;n++){ red[n][w]=p1[n]; red[NNODE+n][w]=p2[n]; }
        }
    }
    __syncthreads();
    if(tid < 2*NNODE){
        float s=0.f;
#pragma unroll
        for(int q=0;q<8;q++) s += red[tid][q];
        if(tid < NNODE) s_s1[tid] = s; else s_s2[tid-NNODE] = s;
    }
    __syncthreads();

    if(tid < NNODE){
        int m = tid;
        float col[NNODE];
        float mx = -3.4e38f;
#pragma unroll
        for(int n=0;n<NNODE;n++){
            float e = s_s1[n] + s_s2[m];
            e = (e > 0.f) ? e : ALPHA_SLOPE*e;
            float v = (adj[(size_t)b*NNODE*NNODE + n*NNODE + m] > 0.f) ? e : NEGV;
            col[n] = v;
            mx = fmaxf(mx, v);
        }
        float sum = 0.f;
#pragma unroll
        for(int n=0;n<NNODE;n++){
            col[n] = expf(col[n]-mx);
            sum += col[n];
        }
        float inv = 1.f/sum;
#pragma unroll
        for(int n=0;n<NNODE;n++) satt[n][m] = col[n]*inv;
    }
    __syncthreads();

    {
        unsigned long long hp01[NNODE], hp23[NNODE];
#pragma unroll
        for(int n=0;n<NNODE;n++){ hp01[n]=0ull; hp23[n]=0ull; }
#pragma unroll
        for(int m=0;m<NNODE;m++){
            float4 wv = *(const float4*)(&sWh[m*K1_PITCH + c0]);
            unsigned long long w01 = pk2(wv.x,wv.y);
            unsigned long long w23 = pk2(wv.z,wv.w);
#pragma unroll
            for(int n=0;n<NNODE;n++){
                float at = satt[n][m];
                unsigned long long ap = pk2(at,at);
                fma2(hp01[n], ap, w01);
                fma2(hp23[n], ap, w23);
            }
        }
        float* outp = g_hp + (size_t)hb * NF + c0;
#pragma unroll
        for(int n=0;n<NNODE;n++){
            float2 q0 = upk(hp01[n]);
            float2 q1 = upk(hp23[n]);
            *(float4*)(outp + (size_t)n*FF) = make_float4(q0.x,q0.y,q1.x,q1.y);
        }
    }
}

// ============================================================================
// K3: split-K tf32 GEMM (R7 shape: 256 thr, depth-4, 92 KB, 2 CTAs/SM).
// Grid 304 = 4h x 4ot(256 o's) x 19kc -> exactly 2 CTAs on every SM.
// Variable K-chunks per kc: kc<3 -> 48 sixteens (768 f), else 47 (752 f).
// ============================================================================
#define K3_PITCH 20
#define K3_SMEM ((4*256*K3_PITCH + 4*32*K3_PITCH)*4)   // 92,160 B

__global__ __launch_bounds__(256,2) void k3_fc(const float* __restrict__ fcw){
    extern __shared__ float s3[];
    float* sB = s3;                          // [4][256][20]
    float* sA = s3 + 4*256*K3_PITCH;         // [4][32][20]

    const int blk = blockIdx.x;              // h*76 + ot*19 + kc
    const int h   = blk / 76;
    const int rem = blk % 76;
    const int ot  = rem / 19;
    const int kc  = rem % 19;

    const int niter = (kc < 3) ? 48 : 47;                       // 16-float steps
    const int f0    = 16 * ((kc < 3) ? kc*48 : 3*48 + (kc-3)*47);

    const int tid  = threadIdx.x;
    const int lane = tid & 31;
    const int w    = tid >> 5;

    const float* hpB = g_hp + (size_t)h * BB * NF;
    const float* wB  = fcw  + (size_t)h * FF * NF + (size_t)(ot*256) * NF;

    float acc[2][4][4];
#pragma unroll
    for(int mt=0;mt<2;mt++)
#pragma unroll
    for(int j=0;j<4;j++){ acc[mt][j][0]=0.f; acc[mt][j][1]=0.f; acc[mt][j][2]=0.f; acc[mt][j][3]=0.f; }

    auto issue = [&](int cc){
        const int s  = cc & 3;
        const int fb = f0 + cc*16;
#pragma unroll
        for(int j=0;j<4;j++){
            int idx = tid + j*256;           // 1024 float4 (256 o x 4)
            int o   = idx >> 2;
            int f4  = (idx & 3) << 2;
            cpasync16(su32(&sB[(s*256 + o)*K3_PITCH + f4]), wB + (size_t)o*NF + fb + f4);
        }
        if(tid < 128){
            int bq = tid >> 2;
            int f4 = (tid & 3) << 2;
            cpasync16(su32(&sA[(s*32 + bq)*K3_PITCH + f4]), hpB + (size_t)bq*NF + fb + f4);
        }
        cpcommit();
    };

    // prologue: 3 chunks in flight
    issue(0); issue(1); issue(2);

    const int ak = lane & 3;
    const int ar = lane >> 2;

    for(int c=0;c<niter;c++){
        if(c+2 < niter)      cpwait<2>();
        else if(c+1 < niter) cpwait<1>();
        else                 cpwait<0>();
        __syncthreads();                     // chunk c visible; chunk c-1 consumed by all
        if(c + 3 < niter) issue(c + 3);      // stage (c+3)&3 == (c-1)&3 — safe after sync

        const int s = c & 3;
        const float* sAs = &sA[s*32*K3_PITCH];
        const float* sBs = &sB[s*256*K3_PITCH];
#pragma unroll
        for(int kh=0;kh<2;kh++){
            const int k0 = kh*8;
            unsigned hfr[2][4], lfr[2][4];
#pragma unroll
            for(int mt=0;mt<2;mt++){
                float a0f = sAs[(mt*16 + ar    )*K3_PITCH + k0 + ak];
                float a1f = sAs[(mt*16 + ar + 8)*K3_PITCH + k0 + ak];
                float a2f = sAs[(mt*16 + ar    )*K3_PITCH + k0 + ak + 4];
                float a3f = sAs[(mt*16 + ar + 8)*K3_PITCH + k0 + ak + 4];
                hfr[mt][0] = __float_as_uint(a0f) & TF32_MASK;
                hfr[mt][1] = __float_as_uint(a1f) & TF32_MASK;
                hfr[mt][2] = __float_as_uint(a2f) & TF32_MASK;
                hfr[mt][3] = __float_as_uint(a3f) & TF32_MASK;
                lfr[mt][0] = __float_as_uint(a0f - __uint_as_float(hfr[mt][0]));
                lfr[mt][1] = __float_as_uint(a1f - __uint_as_float(hfr[mt][1]));
                lfr[mt][2] = __float_as_uint(a2f - __uint_as_float(hfr[mt][2]));
                lfr[mt][3] = __float_as_uint(a3f - __uint_as_float(hfr[mt][3]));
            }
#pragma unroll
            for(int j=0;j<4;j++){
                int nb = w*32 + j*8 + (lane>>2);
                unsigned b0 = __float_as_uint(sBs[nb*K3_PITCH + k0 + ak]);
                unsigned b1 = __float_as_uint(sBs[nb*K3_PITCH + k0 + ak + 4]);
                mma_tf32(acc[0][j], hfr[0][0],hfr[0][1],hfr[0][2],hfr[0][3], b0,b1);
                mma_tf32(acc[0][j], lfr[0][0],lfr[0][1],lfr[0][2],lfr[0][3], b0,b1);
                mma_tf32(acc[1][j], hfr[1][0],hfr[1][1],hfr[1][2],hfr[1][3], b0,b1);
                mma_tf32(acc[1][j], lfr[1][0],lfr[1][1],lfr[1][2],lfr[1][3], b0,b1);
            }
        }
    }

    const int kbi = h*19 + kc;
    float* pp = g_part + (size_t)kbi * BB * FF;
#pragma unroll
    for(int mt=0;mt<2;mt++)
#pragma unroll
    for(int j=0;j<4;j++){
        int col = ot*256 + w*32 + j*8 + 2*(lane&3);
        int r   = mt*16 + (lane>>2);
        *(float2*)(pp + (size_t)r*FF + col)     = make_float2(acc[mt][j][0], acc[mt][j][1]);
        *(float2*)(pp + (size_t)(r+8)*FF + col) = make_float2(acc[mt][j][2], acc[mt][j][3]);
    }
}

// ============================================================================
// K4 (fused): out[b,:] = log_softmax( sum_kb part[kb][b][:] + sum_h fcb[h][:] )
// 32 blocks x 1024 threads (1 o per thread), 76 slices.
// ============================================================================
__global__ __launch_bounds__(1024) void k4_out(const float* __restrict__ fcb,
                                               float* __restrict__ out){
    const int b   = blockIdx.x;
    const int o   = threadIdx.x;
    const int wid = o >> 5, lid = o & 31;

    __shared__ float sred[32];

    float s = 0.f;
#pragma unroll 4
    for(int kb=0;kb<KSPLIT;kb++)
        s += g_part[((size_t)kb*BB + b)*FF + o];
    float bias = 0.f;
#pragma unroll
    for(int h=0;h<HH;h++) bias += fcb[h*FF + o];
    float v = s + bias;

    float mx = v;
#pragma unroll
    for(int off=16;off;off>>=1) mx = fmaxf(mx, __shfl_xor_sync(0xFFFFFFFFu, mx, off));
    if(lid==0) sred[wid]=mx;
    __syncthreads();
    if(wid==0){
        float m = sred[lid];
#pragma unroll
        for(int off=16;off;off>>=1) m = fmaxf(m, __shfl_xor_sync(0xFFFFFFFFu, m, off));
        if(lid==0) sred[0]=m;
    }
    __syncthreads();
    float bm = sred[0];
    __syncthreads();

    float e = expf(v-bm);
    float sm = e;
#pragma unroll
    for(int off=16;off;off>>=1) sm += __shfl_xor_sync(0xFFFFFFFFu, sm, off);
    if(lid==0) sred[wid]=sm;
    __syncthreads();
    if(wid==0){
        float t = sred[lid];
#pragma unroll
        for(int off=16;off;off>>=1) t += __shfl_xor_sync(0xFFFFFFFFu, t, off);
        if(lid==0) sred[0]=t;
    }
    __syncthreads();
    float lse = bm + logf(sred[0]);

    out[(size_t)b*FF + o] = v - lse;
}

// ============================================================================
extern "C" void kernel_launch(void* const* d_in, const int* in_sizes, int n_in,
                              void* d_out, int out_size){
    const float* x   = (const float*)d_in[0];
    const float* adj = (const float*)d_in[1];
    const float* W   = (const float*)d_in[2];
    const float* a   = (const float*)d_in[3];
    const float* fcw = (const float*)d_in[4];
    const float* fcb = (const float*)d_in[5];
    float* out = (float*)d_out;

    cudaFuncSetAttribute(k1_wh, cudaFuncAttributeMaxDynamicSharedMemorySize, K1_SMEM);
    cudaFuncSetAttribute(k3_fc, cudaFuncAttributeMaxDynamicSharedMemorySize, K3_SMEM);

    k1_wh <<<HH*BB, 256, K1_SMEM>>>(x, W, adj, a);
    k3_fc <<<304, 256, K3_SMEM>>>(fcw);
    k4_out<<<BB, 1024>>>(fcb, out);
}

// round 10
// speedup vs baseline: 1.1550x; 1.0055x over previous
#include <cuda_runtime.h>

#define HH 4
#define BB 32
#define NNODE 14
#define FF 1024
#define NF (NNODE*FF)   // 14336
#define KSPLIT 76       // k3 partial slices (h*19 + kc)

#define ALPHA_SLOPE 0.2f
#define NEGV (-9000000000000000.0f)

// Scratch (no allocation allowed)
static __device__ float g_hp[HH*BB*NNODE*FF];     // 7 MB
static __device__ float g_part[KSPLIT*BB*FF];     // 9.5 MB

// ---- packed fp32x2 helpers ----
__device__ __forceinline__ unsigned long long pk2(float a, float b){
    unsigned long long r;
    asm("mov.b64 %0, {%1, %2};" : "=l"(r) : "f"(a), "f"(b));
    return r;
}
__device__ __forceinline__ void fma2(unsigned long long &d, unsigned long long a, unsigned long long b){
    asm("fma.rn.f32x2 %0, %1, %2, %0;" : "+l"(d) : "l"(a), "l"(b));
}
__device__ __forceinline__ float2 upk(unsigned long long v){
    float2 r;
    asm("mov.b64 {%0, %1}, %2;" : "=f"(r.x), "=f"(r.y) : "l"(v));
    return r;
}

// ---- cp.async helpers ----
__device__ __forceinline__ unsigned su32(const void* p){
    return (unsigned)__cvta_generic_to_shared(p);
}
__device__ __forceinline__ void cpasync16(unsigned dst, const void* src){
    asm volatile("cp.async.cg.shared.global [%0], [%1], 16;\n" :: "r"(dst), "l"(src));
}
__device__ __forceinline__ void cpcommit(){ asm volatile("cp.async.commit_group;\n" ::: "memory"); }
template<int N> __device__ __forceinline__ void cpwait(){
    asm volatile("cp.async.wait_group %0;\n" :: "n"(N) : "memory");
}

// ---- tf32 mma.sync (m16n8k8), D += A*B, fp32 accum ----
__device__ __forceinline__ void mma_tf32(float* d,
    unsigned a0, unsigned a1, unsigned a2, unsigned a3,
    unsigned b0, unsigned b1){
    asm volatile("mma.sync.aligned.m16n8k8.row.col.f32.tf32.tf32.f32 "
        "{%0,%1,%2,%3}, {%4,%5,%6,%7}, {%8,%9}, {%0,%1,%2,%3};\n"
        : "+f"(d[0]), "+f"(d[1]), "+f"(d[2]), "+f"(d[3])
        : "r"(a0), "r"(a1), "r"(a2), "r"(a3), "r"(b0), "r"(b1));
}

#define TF32_MASK 0xFFFFE000u   // keep sign+exp+top10 mantissa

// ============================================================================
// K1 (fused with attention) — profiled at 6.2+ TB/s (HBM roofline): UNCHANGED.
// Full hi/lo A-split retained here (feeds softmax; precision-critical).
// ============================================================================
#define K1_PITCH 1032
#define K1_SMEM ((16*K1_PITCH + 2*16*K1_PITCH)*4)

__global__ __launch_bounds__(256) void k1_wh(const float* __restrict__ x,
                                             const float* __restrict__ W,
                                             const float* __restrict__ adj,
                                             const float* __restrict__ attv){
    extern __shared__ float smem[];
    float* sA = smem;                       // [16][1032]
    float* sB = smem + 16*K1_PITCH;         // [2][16][1032]

    __shared__ float s_s1[NNODE], s_s2[NNODE];
    __shared__ float satt[NNODE][NNODE];
    __shared__ float red[2*NNODE][8];

    const int hb   = blockIdx.x;
    const int b    = hb & (BB-1);
    const int tid  = threadIdx.x;
    const int lane = tid & 31;
    const int w    = tid >> 5;

    const float* xb = x + (size_t)b * NNODE * FF;
    const float* Wp = W + (size_t)hb * FF * FF;

    float acc[16][4];
#pragma unroll
    for(int j=0;j<16;j++){ acc[j][0]=0.f; acc[j][1]=0.f; acc[j][2]=0.f; acc[j][3]=0.f; }

    {
#pragma unroll
        for(int j=0;j<16;j++){
            int idx = tid + j*256;
            int r   = idx >> 8;
            int n4  = (idx & 255) << 2;
            cpasync16(su32(&sB[r*K1_PITCH + n4]), Wp + r*FF + n4);
        }
        cpcommit();
    }

#pragma unroll
    for(int j=0;j<16;j++){
        int idx = tid + j*256;
        int r   = idx >> 8;
        int k4  = (idx & 255) << 2;
        float4 v = make_float4(0.f,0.f,0.f,0.f);
        if(r < NNODE) v = *(const float4*)(xb + r*FF + k4);
        *(float4*)(&sA[r*K1_PITCH + k4]) = v;
    }

    const int ar = lane >> 2;
    const int ak = lane & 3;

    for(int c=0;c<64;c++){
        const int buf = c & 1;
        if(c < 63){
            const float* src = Wp + (size_t)(c+1)*16*FF;
#pragma unroll
            for(int j=0;j<16;j++){
                int idx = tid + j*256;
                int r   = idx >> 8;
                int n4  = (idx & 255) << 2;
                cpasync16(su32(&sB[((buf^1)*16 + r)*K1_PITCH + n4]), src + r*FF + n4);
            }
            cpcommit();
            cpwait<1>();
        } else {
            cpwait<0>();
        }
        __syncthreads();

        const float* Bb = &sB[buf*16*K1_PITCH];
#pragma unroll
        for(int kh=0;kh<2;kh++){
            const int k0 = kh*8;
            const int ac = c*16 + k0 + ak;
            float a0f = sA[ar*K1_PITCH + ac];
            float a1f = sA[(ar+8)*K1_PITCH + ac];
            float a2f = sA[ar*K1_PITCH + ac + 4];
            float a3f = sA[(ar+8)*K1_PITCH + ac + 4];
            unsigned h0 = __float_as_uint(a0f) & TF32_MASK;
            unsigned h1 = __float_as_uint(a1f) & TF32_MASK;
            unsigned h2 = __float_as_uint(a2f) & TF32_MASK;
            unsigned h3 = __float_as_uint(a3f) & TF32_MASK;
            unsigned l0 = __float_as_uint(a0f - __uint_as_float(h0));
            unsigned l1 = __float_as_uint(a1f - __uint_as_float(h1));
            unsigned l2 = __float_as_uint(a2f - __uint_as_float(h2));
            unsigned l3 = __float_as_uint(a3f - __uint_as_float(h3));
#pragma unroll
            for(int j=0;j<16;j++){
                int nb = w*128 + j*8 + (lane>>2);
                unsigned b0 = __float_as_uint(Bb[(k0 + ak)*K1_PITCH + nb]);
                unsigned b1 = __float_as_uint(Bb[(k0 + ak + 4)*K1_PITCH + nb]);
                mma_tf32(acc[j], h0,h1,h2,h3, b0,b1);
                mma_tf32(acc[j], l0,l1,l2,l3, b0,b1);
            }
        }
        __syncthreads();
    }

    // ---- fused attention epilogue ----
    float* sWh = sB;   // [16][1032]
    {
        const int r0 = lane >> 2;
#pragma unroll
        for(int j=0;j<16;j++){
            int col = w*128 + j*8 + 2*(lane&3);
            sWh[r0*K1_PITCH + col]     = acc[j][0];
            sWh[r0*K1_PITCH + col + 1] = acc[j][1];
            sWh[(r0+8)*K1_PITCH + col]     = acc[j][2];
            sWh[(r0+8)*K1_PITCH + col + 1] = acc[j][3];
        }
    }
    __syncthreads();

    const int c0 = tid * 4;
    const float* av = attv + (size_t)hb * 2 * FF;
    {
        float4 a1v = *(const float4*)(av + c0);
        float4 a2v = *(const float4*)(av + FF + c0);
        float p1[NNODE], p2[NNODE];
#pragma unroll
        for(int n=0;n<NNODE;n++){
            float4 wv = *(const float4*)(&sWh[n*K1_PITCH + c0]);
            p1[n] = wv.x*a1v.x + wv.y*a1v.y + wv.z*a1v.z + wv.w*a1v.w;
            p2[n] = wv.x*a2v.x + wv.y*a2v.y + wv.z*a2v.z + wv.w*a2v.w;
        }
#pragma unroll
        for(int n=0;n<NNODE;n++){
#pragma unroll
            for(int off=16;off;off>>=1){
                p1[n] += __shfl_xor_sync(0xFFFFFFFFu, p1[n], off);
                p2[n] += __shfl_xor_sync(0xFFFFFFFFu, p2[n], off);
            }
        }
        if(lane==0){
#pragma unroll
            for(int n=0;n<NNODE;n++){ red[n][w]=p1[n]; red[NNODE+n][w]=p2[n]; }
        }
    }
    __syncthreads();
    if(tid < 2*NNODE){
        float s=0.f;
#pragma unroll
        for(int q=0;q<8;q++) s += red[tid][q];
        if(tid < NNODE) s_s1[tid] = s; else s_s2[tid-NNODE] = s;
    }
    __syncthreads();

    if(tid < NNODE){
        int m = tid;
        float col[NNODE];
        float mx = -3.4e38f;
#pragma unroll
        for(int n=0;n<NNODE;n++){
            float e = s_s1[n] + s_s2[m];
            e = (e > 0.f) ? e : ALPHA_SLOPE*e;
            float v = (adj[(size_t)b*NNODE*NNODE + n*NNODE + m] > 0.f) ? e : NEGV;
            col[n] = v;
            mx = fmaxf(mx, v);
        }
        float sum = 0.f;
#pragma unroll
        for(int n=0;n<NNODE;n++){
            col[n] = expf(col[n]-mx);
            sum += col[n];
        }
        float inv = 1.f/sum;
#pragma unroll
        for(int n=0;n<NNODE;n++) satt[n][m] = col[n]*inv;
    }
    __syncthreads();

    {
        unsigned long long hp01[NNODE], hp23[NNODE];
#pragma unroll
        for(int n=0;n<NNODE;n++){ hp01[n]=0ull; hp23[n]=0ull; }
#pragma unroll
        for(int m=0;m<NNODE;m++){
            float4 wv = *(const float4*)(&sWh[m*K1_PITCH + c0]);
            unsigned long long w01 = pk2(wv.x,wv.y);
            unsigned long long w23 = pk2(wv.z,wv.w);
#pragma unroll
            for(int n=0;n<NNODE;n++){
                float at = satt[n][m];
                unsigned long long ap = pk2(at,at);
                fma2(hp01[n], ap, w01);
                fma2(hp23[n], ap, w23);
            }
        }
        float* outp = g_hp + (size_t)hb * NF + c0;
#pragma unroll
        for(int n=0;n<NNODE;n++){
            float2 q0 = upk(hp01[n]);
            float2 q1 = upk(hp23[n]);
            *(float4*)(outp + (size_t)n*FF) = make_float4(q0.x,q0.y,q1.x,q1.y);
        }
    }
}

// ============================================================================
// K3: split-K tf32 GEMM (256 thr, depth-4, 92 KB, 2 CTAs/SM, grid 304).
// A (hp) now SINGLE tf32 pass (no lo compensation) — halves MMA stream and
// deletes split ALU; error budget moves ~3.1e-4 -> ~4.4e-4 (k3 only).
// ============================================================================
#define K3_PITCH 20
#define K3_SMEM ((4*256*K3_PITCH + 4*32*K3_PITCH)*4)   // 92,160 B

__global__ __launch_bounds__(256,2) void k3_fc(const float* __restrict__ fcw){
    extern __shared__ float s3[];
    float* sB = s3;                          // [4][256][20]
    float* sA = s3 + 4*256*K3_PITCH;         // [4][32][20]

    const int blk = blockIdx.x;              // h*76 + ot*19 + kc
    const int h   = blk / 76;
    const int rem = blk % 76;
    const int ot  = rem / 19;
    const int kc  = rem % 19;

    const int niter = (kc < 3) ? 48 : 47;                       // 16-float steps
    const int f0    = 16 * ((kc < 3) ? kc*48 : 3*48 + (kc-3)*47);

    const int tid  = threadIdx.x;
    const int lane = tid & 31;
    const int w    = tid >> 5;

    const float* hpB = g_hp + (size_t)h * BB * NF;
    const float* wB  = fcw  + (size_t)h * FF * NF + (size_t)(ot*256) * NF;

    float acc[2][4][4];
#pragma unroll
    for(int mt=0;mt<2;mt++)
#pragma unroll
    for(int j=0;j<4;j++){ acc[mt][j][0]=0.f; acc[mt][j][1]=0.f; acc[mt][j][2]=0.f; acc[mt][j][3]=0.f; }

    auto issue = [&](int cc){
        const int s  = cc & 3;
        const int fb = f0 + cc*16;
#pragma unroll
        for(int j=0;j<4;j++){
            int idx = tid + j*256;           // 1024 float4 (256 o x 4)
            int o   = idx >> 2;
            int f4  = (idx & 3) << 2;
            cpasync16(su32(&sB[(s*256 + o)*K3_PITCH + f4]), wB + (size_t)o*NF + fb + f4);
        }
        if(tid < 128){
            int bq = tid >> 2;
            int f4 = (tid & 3) << 2;
            cpasync16(su32(&sA[(s*32 + bq)*K3_PITCH + f4]), hpB + (size_t)bq*NF + fb + f4);
        }
        cpcommit();
    };

    // prologue: 3 chunks in flight
    issue(0); issue(1); issue(2);

    const int ak = lane & 3;
    const int ar = lane >> 2;

    for(int c=0;c<niter;c++){
        if(c+2 < niter)      cpwait<2>();
        else if(c+1 < niter) cpwait<1>();
        else                 cpwait<0>();
        __syncthreads();                     // chunk c visible; chunk c-1 consumed by all
        if(c + 3 < niter) issue(c + 3);      // stage (c+3)&3 == (c-1)&3 — safe after sync

        const int s = c & 3;
        const float* sAs = &sA[s*32*K3_PITCH];
        const float* sBs = &sB[s*256*K3_PITCH];
#pragma unroll
        for(int kh=0;kh<2;kh++){
            const int k0 = kh*8;
            unsigned afr[2][4];
#pragma unroll
            for(int mt=0;mt<2;mt++){
                afr[mt][0] = __float_as_uint(sAs[(mt*16 + ar    )*K3_PITCH + k0 + ak]);
                afr[mt][1] = __float_as_uint(sAs[(mt*16 + ar + 8)*K3_PITCH + k0 + ak]);
                afr[mt][2] = __float_as_uint(sAs[(mt*16 + ar    )*K3_PITCH + k0 + ak + 4]);
                afr[mt][3] = __float_as_uint(sAs[(mt*16 + ar + 8)*K3_PITCH + k0 + ak + 4]);
            }
#pragma unroll
            for(int j=0;j<4;j++){
                int nb = w*32 + j*8 + (lane>>2);
                unsigned b0 = __float_as_uint(sBs[nb*K3_PITCH + k0 + ak]);
                unsigned b1 = __float_as_uint(sBs[nb*K3_PITCH + k0 + ak + 4]);
                mma_tf32(acc[0][j], afr[0][0],afr[0][1],afr[0][2],afr[0][3], b0,b1);
                mma_tf32(acc[1][j], afr[1][0],afr[1][1],afr[1][2],afr[1][3], b0,b1);
            }
        }
    }

    const int kbi = h*19 + kc;
    float* pp = g_part + (size_t)kbi * BB * FF;
#pragma unroll
    for(int mt=0;mt<2;mt++)
#pragma unroll
    for(int j=0;j<4;j++){
        int col = ot*256 + w*32 + j*8 + 2*(lane&3);
        int r   = mt*16 + (lane>>2);
        *(float2*)(pp + (size_t)r*FF + col)     = make_float2(acc[mt][j][0], acc[mt][j][1]);
        *(float2*)(pp + (size_t)(r+8)*FF + col) = make_float2(acc[mt][j][2], acc[mt][j][3]);
    }
}

// ============================================================================
// K4 (fused): out[b,:] = log_softmax( sum_kb part[kb][b][:] + sum_h fcb[h][:] )
// 32 blocks x 1024 threads (1 o per thread), 76 slices.
// ============================================================================
__global__ __launch_bounds__(1024) void k4_out(const float* __restrict__ fcb,
                                               float* __restrict__ out){
    const int b   = blockIdx.x;
    const int o   = threadIdx.x;
    const int wid = o >> 5, lid = o & 31;

    __shared__ float sred[32];

    float s = 0.f;
#pragma unroll 4
    for(int kb=0;kb<KSPLIT;kb++)
        s += g_part[((size_t)kb*BB + b)*FF + o];
    float bias = 0.f;
#pragma unroll
    for(int h=0;h<HH;h++) bias += fcb[h*FF + o];
    float v = s + bias;

    float mx = v;
#pragma unroll
    for(int off=16;off;off>>=1) mx = fmaxf(mx, __shfl_xor_sync(0xFFFFFFFFu, mx, off));
    if(lid==0) sred[wid]=mx;
    __syncthreads();
    if(wid==0){
        float m = sred[lid];
#pragma unroll
        for(int off=16;off;off>>=1) m = fmaxf(m, __shfl_xor_sync(0xFFFFFFFFu, m, off));
        if(lid==0) sred[0]=m;
    }
    __syncthreads();
    float bm = sred[0];
    __syncthreads();

    float e = expf(v-bm);
    float sm = e;
#pragma unroll
    for(int off=16;off;off>>=1) sm += __shfl_xor_sync(0xFFFFFFFFu, sm, off);
    if(lid==0) sred[wid]=sm;
    __syncthreads();
    if(wid==0){
        float t = sred[lid];
#pragma unroll
        for(int off=16;off;off>>=1) t += __shfl_xor_sync(0xFFFFFFFFu, t, off);
        if(lid==0) sred[0]=t;
    }
    __syncthreads();
    float lse = bm + logf(sred[0]);

    out[(size_t)b*FF + o] = v - lse;
}

// ============================================================================
extern "C" void kernel_launch(void* const* d_in, const int* in_sizes, int n_in,
                              void* d_out, int out_size){
    const float* x   = (const float*)d_in[0];
    const float* adj = (const float*)d_in[1];
    const float* W   = (const float*)d_in[2];
    const float* a   = (const float*)d_in[3];
    const float* fcw = (const float*)d_in[4];
    const float* fcb = (const float*)d_in[5];
    float* out = (float*)d_out;

    cudaFuncSetAttribute(k1_wh, cudaFuncAttributeMaxDynamicSharedMemorySize, K1_SMEM);
    cudaFuncSetAttribute(k3_fc, cudaFuncAttributeMaxDynamicSharedMemorySize, K3_SMEM);

    k1_wh <<<HH*BB, 256, K1_SMEM>>>(x, W, adj, a);
    k3_fc <<<304, 256, K3_SMEM>>>(fcw);
    k4_out<<<BB, 1024>>>(fcb, out);
}

// round 11
// speedup vs baseline: 1.1994x; 1.0384x over previous
#include <cuda_runtime.h>

#define HH 4
#define BB 32
#define NNODE 14
#define FF 1024
#define NF (NNODE*FF)   // 14336
#define KSPLIT 76       // k3 partial slices (h*19 + kc)

#define ALPHA_SLOPE 0.2f
#define NEGV (-9000000000000000.0f)

// Scratch (no allocation allowed)
static __device__ float g_hp[HH*BB*NNODE*FF];     // 7 MB
static __device__ float g_part[KSPLIT*BB*FF];     // 9.5 MB

// ---- packed fp32x2 helpers ----
__device__ __forceinline__ unsigned long long pk2(float a, float b){
    unsigned long long r;
    asm("mov.b64 %0, {%1, %2};" : "=l"(r) : "f"(a), "f"(b));
    return r;
}
__device__ __forceinline__ void fma2(unsigned long long &d, unsigned long long a, unsigned long long b){
    asm("fma.rn.f32x2 %0, %1, %2, %0;" : "+l"(d) : "l"(a), "l"(b));
}
__device__ __forceinline__ float2 upk(unsigned long long v){
    float2 r;
    asm("mov.b64 {%0, %1}, %2;" : "=f"(r.x), "=f"(r.y) : "l"(v));
    return r;
}

// ---- cp.async helpers ----
__device__ __forceinline__ unsigned su32(const void* p){
    return (unsigned)__cvta_generic_to_shared(p);
}
__device__ __forceinline__ void cpasync16(unsigned dst, const void* src){
    asm volatile("cp.async.cg.shared.global [%0], [%1], 16;\n" :: "r"(dst), "l"(src));
}
__device__ __forceinline__ void cpcommit(){ asm volatile("cp.async.commit_group;\n" ::: "memory"); }
template<int N> __device__ __forceinline__ void cpwait(){
    asm volatile("cp.async.wait_group %0;\n" :: "n"(N) : "memory");
}

// ---- tf32 mma.sync (m16n8k8), D += A*B, fp32 accum ----
__device__ __forceinline__ void mma_tf32(float* d,
    unsigned a0, unsigned a1, unsigned a2, unsigned a3,
    unsigned b0, unsigned b1){
    asm volatile("mma.sync.aligned.m16n8k8.row.col.f32.tf32.tf32.f32 "
        "{%0,%1,%2,%3}, {%4,%5,%6,%7}, {%8,%9}, {%0,%1,%2,%3};\n"
        : "+f"(d[0]), "+f"(d[1]), "+f"(d[2]), "+f"(d[3])
        : "r"(a0), "r"(a1), "r"(a2), "r"(a3), "r"(b0), "r"(b1));
}

#define TF32_MASK 0xFFFFE000u   // keep sign+exp+top10 mantissa

// ============================================================================
// K1 (fused with attention) — profiled at 6.2+ TB/s (HBM roofline): UNCHANGED.
// ============================================================================
#define K1_PITCH 1032
#define K1_SMEM ((16*K1_PITCH + 2*16*K1_PITCH)*4)

__global__ __launch_bounds__(256) void k1_wh(const float* __restrict__ x,
                                             const float* __restrict__ W,
                                             const float* __restrict__ adj,
                                             const float* __restrict__ attv){
    extern __shared__ float smem[];
    float* sA = smem;                       // [16][1032]
    float* sB = smem + 16*K1_PITCH;         // [2][16][1032]

    __shared__ float s_s1[NNODE], s_s2[NNODE];
    __shared__ float satt[NNODE][NNODE];
    __shared__ float red[2*NNODE][8];

    const int hb   = blockIdx.x;
    const int b    = hb & (BB-1);
    const int tid  = threadIdx.x;
    const int lane = tid & 31;
    const int w    = tid >> 5;

    const float* xb = x + (size_t)b * NNODE * FF;
    const float* Wp = W + (size_t)hb * FF * FF;

    float acc[16][4];
#pragma unroll
    for(int j=0;j<16;j++){ acc[j][0]=0.f; acc[j][1]=0.f; acc[j][2]=0.f; acc[j][3]=0.f; }

    {
#pragma unroll
        for(int j=0;j<16;j++){
            int idx = tid + j*256;
            int r   = idx >> 8;
            int n4  = (idx & 255) << 2;
            cpasync16(su32(&sB[r*K1_PITCH + n4]), Wp + r*FF + n4);
        }
        cpcommit();
    }

#pragma unroll
    for(int j=0;j<16;j++){
        int idx = tid + j*256;
        int r   = idx >> 8;
        int k4  = (idx & 255) << 2;
        float4 v = make_float4(0.f,0.f,0.f,0.f);
        if(r < NNODE) v = *(const float4*)(xb + r*FF + k4);
        *(float4*)(&sA[r*K1_PITCH + k4]) = v;
    }

    const int ar = lane >> 2;
    const int ak = lane & 3;

    for(int c=0;c<64;c++){
        const int buf = c & 1;
        if(c < 63){
            const float* src = Wp + (size_t)(c+1)*16*FF;
#pragma unroll
            for(int j=0;j<16;j++){
                int idx = tid + j*256;
                int r   = idx >> 8;
                int n4  = (idx & 255) << 2;
                cpasync16(su32(&sB[((buf^1)*16 + r)*K1_PITCH + n4]), src + r*FF + n4);
            }
            cpcommit();
            cpwait<1>();
        } else {
            cpwait<0>();
        }
        __syncthreads();

        const float* Bb = &sB[buf*16*K1_PITCH];
#pragma unroll
        for(int kh=0;kh<2;kh++){
            const int k0 = kh*8;
            const int ac = c*16 + k0 + ak;
            float a0f = sA[ar*K1_PITCH + ac];
            float a1f = sA[(ar+8)*K1_PITCH + ac];
            float a2f = sA[ar*K1_PITCH + ac + 4];
            float a3f = sA[(ar+8)*K1_PITCH + ac + 4];
            unsigned h0 = __float_as_uint(a0f) & TF32_MASK;
            unsigned h1 = __float_as_uint(a1f) & TF32_MASK;
            unsigned h2 = __float_as_uint(a2f) & TF32_MASK;
            unsigned h3 = __float_as_uint(a3f) & TF32_MASK;
            unsigned l0 = __float_as_uint(a0f - __uint_as_float(h0));
            unsigned l1 = __float_as_uint(a1f - __uint_as_float(h1));
            unsigned l2 = __float_as_uint(a2f - __uint_as_float(h2));
            unsigned l3 = __float_as_uint(a3f - __uint_as_float(h3));
#pragma unroll
            for(int j=0;j<16;j++){
                int nb = w*128 + j*8 + (lane>>2);
                unsigned b0 = __float_as_uint(Bb[(k0 + ak)*K1_PITCH + nb]);
                unsigned b1 = __float_as_uint(Bb[(k0 + ak + 4)*K1_PITCH + nb]);
                mma_tf32(acc[j], h0,h1,h2,h3, b0,b1);
                mma_tf32(acc[j], l0,l1,l2,l3, b0,b1);
            }
        }
        __syncthreads();
    }

    // ---- fused attention epilogue ----
    float* sWh = sB;   // [16][1032]
    {
        const int r0 = lane >> 2;
#pragma unroll
        for(int j=0;j<16;j++){
            int col = w*128 + j*8 + 2*(lane&3);
            sWh[r0*K1_PITCH + col]     = acc[j][0];
            sWh[r0*K1_PITCH + col + 1] = acc[j][1];
            sWh[(r0+8)*K1_PITCH + col]     = acc[j][2];
            sWh[(r0+8)*K1_PITCH + col + 1] = acc[j][3];
        }
    }
    __syncthreads();

    const int c0 = tid * 4;
    const float* av = attv + (size_t)hb * 2 * FF;
    {
        float4 a1v = *(const float4*)(av + c0);
        float4 a2v = *(const float4*)(av + FF + c0);
        float p1[NNODE], p2[NNODE];
#pragma unroll
        for(int n=0;n<NNODE;n++){
            float4 wv = *(const float4*)(&sWh[n*K1_PITCH + c0]);
            p1[n] = wv.x*a1v.x + wv.y*a1v.y + wv.z*a1v.z + wv.w*a1v.w;
            p2[n] = wv.x*a2v.x + wv.y*a2v.y + wv.z*a2v.z + wv.w*a2v.w;
        }
#pragma unroll
        for(int n=0;n<NNODE;n++){
#pragma unroll
            for(int off=16;off;off>>=1){
                p1[n] += __shfl_xor_sync(0xFFFFFFFFu, p1[n], off);
                p2[n] += __shfl_xor_sync(0xFFFFFFFFu, p2[n], off);
            }
        }
        if(lane==0){
#pragma unroll
            for(int n=0;n<NNODE;n++){ red[n][w]=p1[n]; red[NNODE+n][w]=p2[n]; }
        }
    }
    __syncthreads();
    if(tid < 2*NNODE){
        float s=0.f;
#pragma unroll
        for(int q=0;q<8;q++) s += red[tid][q];
        if(tid < NNODE) s_s1[tid] = s; else s_s2[tid-NNODE] = s;
    }
    __syncthreads();

    if(tid < NNODE){
        int m = tid;
        float col[NNODE];
        float mx = -3.4e38f;
#pragma unroll
        for(int n=0;n<NNODE;n++){
            float e = s_s1[n] + s_s2[m];
            e = (e > 0.f) ? e : ALPHA_SLOPE*e;
            float v = (adj[(size_t)b*NNODE*NNODE + n*NNODE + m] > 0.f) ? e : NEGV;
            col[n] = v;
            mx = fmaxf(mx, v);
        }
        float sum = 0.f;
#pragma unroll
        for(int n=0;n<NNODE;n++){
            col[n] = expf(col[n]-mx);
            sum += col[n];
        }
        float inv = 1.f/sum;
#pragma unroll
        for(int n=0;n<NNODE;n++) satt[n][m] = col[n]*inv;
    }
    __syncthreads();

    {
        unsigned long long hp01[NNODE], hp23[NNODE];
#pragma unroll
        for(int n=0;n<NNODE;n++){ hp01[n]=0ull; hp23[n]=0ull; }
#pragma unroll
        for(int m=0;m<NNODE;m++){
            float4 wv = *(const float4*)(&sWh[m*K1_PITCH + c0]);
            unsigned long long w01 = pk2(wv.x,wv.y);
            unsigned long long w23 = pk2(wv.z,wv.w);
#pragma unroll
            for(int n=0;n<NNODE;n++){
                float at = satt[n][m];
                unsigned long long ap = pk2(at,at);
                fma2(hp01[n], ap, w01);
                fma2(hp23[n], ap, w23);
            }
        }
        float* outp = g_hp + (size_t)hb * NF + c0;
#pragma unroll
        for(int n=0;n<NNODE;n++){
            float2 q0 = upk(hp01[n]);
            float2 q1 = upk(hp23[n]);
            *(float4*)(outp + (size_t)n*FF) = make_float4(q0.x,q0.y,q1.x,q1.y);
        }
    }
}

// ============================================================================
// K3: split-K tf32 GEMM. NEW: o_tile=128, k_chunk=32 floats (128 B per row
// per iter -> full-line LDGSTS wavefronts, halved L1tex/LTS request rate).
// Same 92 KB smem, depth-4, 2 CTAs/SM, grid 304; each CTA runs 2 of the
// 608 work items (4h x 8ot x 19kc). A single-pass tf32 (as R10).
// ============================================================================
#define K3_PITCH 36
#define K3_SMEM ((4*128*K3_PITCH + 4*32*K3_PITCH)*4)   // 92,160 B

__global__ __launch_bounds__(256,2) void k3_fc(const float* __restrict__ fcw){
    extern __shared__ float s3[];
    float* sB = s3;                          // [4][128][36]
    float* sA = s3 + 4*128*K3_PITCH;         // [4][32][36]

    const int tid  = threadIdx.x;
    const int lane = tid & 31;
    const int w    = tid >> 5;
    const int ak = lane & 3;
    const int ar = lane >> 2;

#pragma unroll 1
    for(int itq=0; itq<2; itq++){
        const int it  = blockIdx.x + itq*304;    // 0..607
        const int h   = it / 152;
        const int rem = it % 152;
        const int ot  = rem / 19;                // 0..7 (128-o tiles)
        const int kc  = rem % 19;

        const int niter = (kc < 11) ? 24 : 23;                       // 32-float steps
        const int f0    = 32 * ((kc < 11) ? kc*24 : 11*24 + (kc-11)*23);

        const float* hpB = g_hp + (size_t)h * BB * NF;
        const float* wB  = fcw  + (size_t)h * FF * NF + (size_t)(ot*128) * NF;

        float acc[2][2][4];
#pragma unroll
        for(int mt=0;mt<2;mt++)
#pragma unroll
        for(int j=0;j<2;j++){ acc[mt][j][0]=0.f; acc[mt][j][1]=0.f; acc[mt][j][2]=0.f; acc[mt][j][3]=0.f; }

        auto issue = [&](int cc){
            const int s  = cc & 3;
            const int fb = f0 + cc*32;
#pragma unroll
            for(int j=0;j<4;j++){
                int idx = tid + j*256;           // 1024 float4 (128 o x 8)
                int o   = idx >> 3;              // 0..127
                int f4  = (idx & 7) << 2;        // 0..28 floats (128 B contiguous)
                cpasync16(su32(&sB[(s*128 + o)*K3_PITCH + f4]), wB + (size_t)o*NF + fb + f4);
            }
            {   // A: 32 rows x 32 floats = 256 float4, all threads
                int bq = tid >> 3;
                int f4 = (tid & 7) << 2;
                cpasync16(su32(&sA[(s*32 + bq)*K3_PITCH + f4]), hpB + (size_t)bq*NF + fb + f4);
            }
            cpcommit();
        };

        issue(0); issue(1); issue(2);

        for(int c=0;c<niter;c++){
            if(c+2 < niter)      cpwait<2>();
            else if(c+1 < niter) cpwait<1>();
            else                 cpwait<0>();
            __syncthreads();
            if(c + 3 < niter) issue(c + 3);

            const int s = c & 3;
            const float* sAs = &sA[s*32*K3_PITCH];
            const float* sBs = &sB[s*128*K3_PITCH];
#pragma unroll
            for(int kh=0;kh<4;kh++){
                const int k0 = kh*8;
                unsigned afr[2][4];
#pragma unroll
                for(int mt=0;mt<2;mt++){
                    afr[mt][0] = __float_as_uint(sAs[(mt*16 + ar    )*K3_PITCH + k0 + ak]);
                    afr[mt][1] = __float_as_uint(sAs[(mt*16 + ar + 8)*K3_PITCH + k0 + ak]);
                    afr[mt][2] = __float_as_uint(sAs[(mt*16 + ar    )*K3_PITCH + k0 + ak + 4]);
                    afr[mt][3] = __float_as_uint(sAs[(mt*16 + ar + 8)*K3_PITCH + k0 + ak + 4]);
                }
#pragma unroll
                for(int j=0;j<2;j++){
                    int nb = w*16 + j*8 + (lane>>2);
                    unsigned b0 = __float_as_uint(sBs[nb*K3_PITCH + k0 + ak]);
                    unsigned b1 = __float_as_uint(sBs[nb*K3_PITCH + k0 + ak + 4]);
                    mma_tf32(acc[0][j], afr[0][0],afr[0][1],afr[0][2],afr[0][3], b0,b1);
                    mma_tf32(acc[1][j], afr[1][0],afr[1][1],afr[1][2],afr[1][3], b0,b1);
                }
            }
        }

        const int kbi = h*19 + kc;
        float* pp = g_part + (size_t)kbi * BB * FF;
#pragma unroll
        for(int mt=0;mt<2;mt++)
#pragma unroll
        for(int j=0;j<2;j++){
            int col = ot*128 + w*16 + j*8 + 2*(lane&3);
            int r   = mt*16 + (lane>>2);
            *(float2*)(pp + (size_t)r*FF + col)     = make_float2(acc[mt][j][0], acc[mt][j][1]);
            *(float2*)(pp + (size_t)(r+8)*FF + col) = make_float2(acc[mt][j][2], acc[mt][j][3]);
        }
        __syncthreads();   // all smem reads done before next item's issue() overwrites
    }
}

// ============================================================================
// K4 (fused): out[b,:] = log_softmax( sum_kb part[kb][b][:] + sum_h fcb[h][:] )
// 32 blocks x 1024 threads; 4 independent accumulators for load MLP.
// ============================================================================
__global__ __launch_bounds__(1024) void k4_out(const float* __restrict__ fcb,
                                               float* __restrict__ out){
    const int b   = blockIdx.x;
    const int o   = threadIdx.x;
    const int wid = o >> 5, lid = o & 31;

    __shared__ float sred[32];

    float s0=0.f, s1=0.f, s2=0.f, s3=0.f;
#pragma unroll 4
    for(int kb=0;kb<KSPLIT;kb+=4){
        s0 += g_part[((size_t)(kb  )*BB + b)*FF + o];
        s1 += g_part[((size_t)(kb+1)*BB + b)*FF + o];
        s2 += g_part[((size_t)(kb+2)*BB + b)*FF + o];
        s3 += g_part[((size_t)(kb+3)*BB + b)*FF + o];
    }
    float bias = 0.f;
#pragma unroll
    for(int h=0;h<HH;h++) bias += fcb[h*FF + o];
    float v = (s0+s1) + (s2+s3) + bias;

    float mx = v;
#pragma unroll
    for(int off=16;off;off>>=1) mx = fmaxf(mx, __shfl_xor_sync(0xFFFFFFFFu, mx, off));
    if(lid==0) sred[wid]=mx;
    __syncthreads();
    if(wid==0){
        float m = sred[lid];
#pragma unroll
        for(int off=16;off;off>>=1) m = fmaxf(m, __shfl_xor_sync(0xFFFFFFFFu, m, off));
        if(lid==0) sred[0]=m;
    }
    __syncthreads();
    float bm = sred[0];
    __syncthreads();

    float e = expf(v-bm);
    float sm = e;
#pragma unroll
    for(int off=16;off;off>>=1) sm += __shfl_xor_sync(0xFFFFFFFFu, sm, off);
    if(lid==0) sred[wid]=sm;
    __syncthreads();
    if(wid==0){
        float t = sred[lid];
#pragma unroll
        for(int off=16;off;off>>=1) t += __shfl_xor_sync(0xFFFFFFFFu, t, off);
        if(lid==0) sred[0]=t;
    }
    __syncthreads();
    float lse = bm + logf(sred[0]);

    out[(size_t)b*FF + o] = v - lse;
}

// ============================================================================
extern "C" void kernel_launch(void* const* d_in, const int* in_sizes, int n_in,
                              void* d_out, int out_size){
    const float* x   = (const float*)d_in[0];
    const float* adj = (const float*)d_in[1];
    const float* W   = (const float*)d_in[2];
    const float* a   = (const float*)d_in[3];
    const float* fcw = (const float*)d_in[4];
    const float* fcb = (const float*)d_in[5];
    float* out = (float*)d_out;

    cudaFuncSetAttribute(k1_wh, cudaFuncAttributeMaxDynamicSharedMemorySize, K1_SMEM);
    cudaFuncSetAttribute(k3_fc, cudaFuncAttributeMaxDynamicSharedMemorySize, K3_SMEM);

    k1_wh <<<HH*BB, 256, K1_SMEM>>>(x, W, adj, a);
    k3_fc <<<304, 256, K3_SMEM>>>(fcw);
    k4_out<<<BB, 1024>>>(fcb, out);
}